// round 7
// baseline (speedup 1.0000x reference)
#include <cuda_runtime.h>
#include <cuda_bf16.h>
#include <cstddef>

// out[e] = let v = sigmoid(cos(emb[i1],emb[i2])/T) in (v <= 0.5 ? 0 : v)
//
// R5 ncu: edge kernel sits exactly at the B300 LTS cap (~6300 B/cyc);
// only lever = fewer L2 bytes. fp32 is mandatory (one 0.5-threshold sign
// flip costs rel_err ~9e-4). So: counting-sort edges by src node, then
// warp-per-node kernel loads the 256B src row ONCE into registers and
// streams dst gathers. Src gather traffic drops 512MB -> 25.6MB.
//
// Pipeline (7 launches, one graph, no allocs - __device__ globals):
//  1 norm_zero : rinv[n]=1/max(||emb[n]||,eps); zero counters
//  2 hist      : count[src]++
//  3 scan_a/b/c: exclusive prefix -> offset[], cursor[]
//  4 scatter   : sorted[atomicAdd(cursor[src])] = (dst, eid)
//  5 edge      : warp w = node w; src row in regs; loop dst list

#define NODE_CAP (1 << 17)   // 131072  (N = 100000)
#define EDGE_CAP (1 << 21)   // 2097152 (E = 2000000)
#define SCAN_BLK 1024

__device__ float g_rinv[NODE_CAP];
__device__ int   g_count[NODE_CAP + 1];
__device__ int   g_offset[NODE_CAP + 1];
__device__ int   g_cursor[NODE_CAP];
__device__ int   g_bsum[NODE_CAP / SCAN_BLK + 2];
__device__ int2  g_sorted[EDGE_CAP];

static __device__ __forceinline__ float decode_scalar(const void* p) {
    if (p == nullptr) return 1.0f;
    int iv = *(const int*)p;
    if (iv > 0 && iv < (1 << 23)) return (float)iv;   // int32-encoded
    return __int_as_float(iv);                        // f32 bits
}

// ---------- pass 1: per-node inverse norm (+ zero histogram) ----------
__global__ void __launch_bounds__(256) norm_zero_kernel(
    const float4* __restrict__ emb, float* __restrict__ rinv,
    int* __restrict__ count, int N)
{
    int tid = blockIdx.x * blockDim.x + threadIdx.x;
    if (tid <= N) count[tid] = 0;
    int nid = tid >> 3;
    int sub = tid & 7;
    if (nid >= N) return;

    const float4* a = emb + (size_t)nid * 16;
    float4 v0 = __ldg(&a[sub]);
    float4 v1 = __ldg(&a[sub + 8]);
    float n = v0.x*v0.x + v0.y*v0.y + v0.z*v0.z + v0.w*v0.w
            + v1.x*v1.x + v1.y*v1.y + v1.z*v1.z + v1.w*v1.w;
    #pragma unroll
    for (int m = 4; m > 0; m >>= 1)
        n += __shfl_xor_sync(0xFFFFFFFFu, n, m);
    if (sub == 0)
        rinv[nid] = 1.0f / fmaxf(sqrtf(n), 1e-6f);
}

// ---------- pass 2: histogram of src ----------
__global__ void __launch_bounds__(256) hist_kernel(
    const int* __restrict__ ei, int* __restrict__ count, int E)
{
    int e = blockIdx.x * blockDim.x + threadIdx.x;
    if (e < E) atomicAdd(&count[__ldg(&ei[e])], 1);
}

// ---------- pass 3: exclusive scan (3 stages) ----------
__global__ void __launch_bounds__(SCAN_BLK) scan_a_kernel(int N)
{
    __shared__ int s[SCAN_BLK];
    int i = blockIdx.x * SCAN_BLK + threadIdx.x;
    int v = (i < N) ? g_count[i] : 0;
    s[threadIdx.x] = v;
    __syncthreads();
    #pragma unroll
    for (int off = 1; off < SCAN_BLK; off <<= 1) {
        int t = (threadIdx.x >= off) ? s[threadIdx.x - off] : 0;
        __syncthreads();
        s[threadIdx.x] += t;
        __syncthreads();
    }
    if (i < N) g_offset[i] = s[threadIdx.x] - v;   // exclusive
    if (threadIdx.x == SCAN_BLK - 1) g_bsum[blockIdx.x] = s[threadIdx.x];
}

__global__ void scan_b_kernel(int nb, int N, int E)
{
    if (threadIdx.x == 0 && blockIdx.x == 0) {
        int acc = 0;
        for (int b = 0; b < nb; b++) { int t = g_bsum[b]; g_bsum[b] = acc; acc += t; }
        g_offset[N] = E;
    }
}

__global__ void __launch_bounds__(SCAN_BLK) scan_c_kernel(int N)
{
    int i = blockIdx.x * SCAN_BLK + threadIdx.x;
    if (i < N) {
        int o = g_offset[i] + g_bsum[blockIdx.x];
        g_offset[i] = o;
        g_cursor[i] = o;
    }
}

// ---------- pass 4: scatter (dst, eid) into src-sorted order ----------
__global__ void __launch_bounds__(256) scatter_kernel(
    const int* __restrict__ ei, int E)
{
    int e = blockIdx.x * blockDim.x + threadIdx.x;
    if (e >= E) return;
    int s = __ldg(&ei[e]);
    int d = __ldg(&ei[E + e]);
    int p = atomicAdd(&g_cursor[s], 1);
    g_sorted[p] = make_int2(d, e);
}

// ---------- pass 5: warp-per-src-node edge kernel ----------
// 8 lanes per edge (full 128B-line LDG.128s), 4 groups/warp, 2 batches per
// iteration for MLP. Src row lives in registers for the whole adjacency list.
__global__ void __launch_bounds__(256) edge_sorted_kernel(
    const float4* __restrict__ emb,
    const float*  __restrict__ rinv,
    const void*   __restrict__ temp,
    float*        __restrict__ out,
    int N)
{
    int gw   = (blockIdx.x * blockDim.x + threadIdx.x) >> 5;
    int lane = threadIdx.x & 31;
    if (gw >= N) return;

    int start = __ldg(&g_offset[gw]);
    int end   = __ldg(&g_offset[gw + 1]);
    if (start >= end) return;

    int sub = lane & 7;
    int grp = lane >> 3;

    const float4* a = emb + (size_t)gw * 16;
    float4 a0 = __ldg(&a[sub]);
    float4 a1 = __ldg(&a[sub + 8]);
    float  rs = __ldg(&rinv[gw]);
    float  invT = 1.0f / decode_scalar(temp);

    for (int base = start; base < end; base += 8) {
        int p1 = base + grp;
        int p2 = base + 4 + grp;
        bool act1 = p1 < end;
        bool act2 = p2 < end;

        int2 de1 = act1 ? __ldg(&g_sorted[p1]) : make_int2(0, 0);
        int2 de2 = act2 ? __ldg(&g_sorted[p2]) : make_int2(0, 0);

        const float4* b1p = emb + (size_t)de1.x * 16;
        const float4* b2p = emb + (size_t)de2.x * 16;
        float4 z = make_float4(0.f, 0.f, 0.f, 0.f);
        float4 b10 = z, b11 = z, b20 = z, b21 = z;
        if (act1) { b10 = __ldg(&b1p[sub]); b11 = __ldg(&b1p[sub + 8]); }
        if (act2) { b20 = __ldg(&b2p[sub]); b21 = __ldg(&b2p[sub + 8]); }

        float d1 = a0.x*b10.x + a0.y*b10.y + a0.z*b10.z + a0.w*b10.w
                 + a1.x*b11.x + a1.y*b11.y + a1.z*b11.z + a1.w*b11.w;
        float d2 = a0.x*b20.x + a0.y*b20.y + a0.z*b20.z + a0.w*b20.w
                 + a1.x*b21.x + a1.y*b21.y + a1.z*b21.z + a1.w*b21.w;

        #pragma unroll
        for (int m = 4; m > 0; m >>= 1) {
            d1 += __shfl_xor_sync(0xFFFFFFFFu, d1, m);
            d2 += __shfl_xor_sync(0xFFFFFFFFu, d2, m);
        }

        if (sub == 0) {
            if (act1) {
                float att = d1 * rs * __ldg(&rinv[de1.x]);
                float v = 1.0f / (1.0f + __expf(-att * invT));
                out[de1.y] = (v <= 0.5f) ? 0.0f : v;
            }
            if (act2) {
                float att = d2 * rs * __ldg(&rinv[de2.x]);
                float v = 1.0f / (1.0f + __expf(-att * invT));
                out[de2.y] = (v <= 0.5f) ? 0.0f : v;
            }
        }
    }
}

// ---------- fallback (R5 path) for sizes beyond the static caps ----------
__global__ void __launch_bounds__(256) edge_kernel_fb(
    const float4* __restrict__ emb, const int* __restrict__ ei,
    const float* __restrict__ rinv, const void* __restrict__ temp,
    float* __restrict__ out, int E)
{
    int tid = blockIdx.x * blockDim.x + threadIdx.x;
    int eid = tid >> 3;
    int sub = tid & 7;
    if (eid >= E) return;
    int i1 = __ldg(&ei[eid]);
    int i2 = __ldg(&ei[E + eid]);
    const float4* a = emb + (size_t)i1 * 16;
    const float4* b = emb + (size_t)i2 * 16;
    float4 a0 = __ldg(&a[sub]), a1 = __ldg(&a[sub + 8]);
    float4 b0 = __ldg(&b[sub]), b1 = __ldg(&b[sub + 8]);
    float dot = a0.x*b0.x + a0.y*b0.y + a0.z*b0.z + a0.w*b0.w
              + a1.x*b1.x + a1.y*b1.y + a1.z*b1.z + a1.w*b1.w;
    #pragma unroll
    for (int m = 4; m > 0; m >>= 1)
        dot += __shfl_xor_sync(0xFFFFFFFFu, dot, m);
    if (sub == 0) {
        float att = dot * __ldg(&rinv[i1]) * __ldg(&rinv[i2]);
        float T = decode_scalar(temp);
        float v = 1.0f / (1.0f + __expf(-att / T));
        out[eid] = (v <= 0.5f) ? 0.0f : v;
    }
}

extern "C" void kernel_launch(void* const* d_in, const int* in_sizes, int n_in,
                              void* d_out, int out_size)
{
    const float4* emb  = (const float4*)d_in[0];
    const int*    ei   = (const int*)d_in[1];
    const void*   temp = (n_in > 2) ? d_in[2] : nullptr;
    float*        out  = (float*)d_out;

    int N = in_sizes[0] / 64;
    int E = in_sizes[1] / 2;

    float* rinv  = nullptr;
    int*   count = nullptr;
    cudaGetSymbolAddress((void**)&rinv,  g_rinv);
    cudaGetSymbolAddress((void**)&count, g_count);

    // pass 1 (also zeroes histogram when in sorted path)
    {
        long long total = (long long)N * 8;
        int blocks = (int)((total + 255) / 256);
        norm_zero_kernel<<<blocks, 256>>>(emb, rinv, count, N);
    }

    if (N <= NODE_CAP && E <= EDGE_CAP) {
        int eb = (E + 255) / 256;
        hist_kernel<<<eb, 256>>>(ei, count, E);

        int nb = (N + SCAN_BLK - 1) / SCAN_BLK;
        scan_a_kernel<<<nb, SCAN_BLK>>>(N);
        scan_b_kernel<<<1, 32>>>(nb, N, E);
        scan_c_kernel<<<nb, SCAN_BLK>>>(N);

        scatter_kernel<<<eb, 256>>>(ei, E);

        long long total = (long long)N * 32;
        int blocks = (int)((total + 255) / 256);
        edge_sorted_kernel<<<blocks, 256>>>(emb, rinv, temp, out, N);
    } else {
        long long total = (long long)E * 8;
        int blocks = (int)((total + 255) / 256);
        edge_kernel_fb<<<blocks, 256>>>(emb, ei, rinv, temp, out, E);
    }
}

// round 8
// speedup vs baseline: 1.6189x; 1.6189x over previous
#include <cuda_runtime.h>
#include <cuda_bf16.h>
#include <cstddef>

// out[e] = let v = sigmoid(cos(emb[i1],emb[i2])/T) in (v <= 0.5 ? 0 : v)
//
// Evidence so far:
//  R5 flat kernel (72.4us) sits at the B300 LTS chip cap -> only byte
//  reduction helps. R7 counting-sort pipeline regressed (116.8us): its
//  theoretical 25% saving was eaten by scattered writes + pre-pass kernels.
//
// This round: stay flat, remove the rinv random gathers (~12% of L2
// sectors) by PRE-NORMALIZING the node table once into a __device__
// scratch array. Edge kernel then reads only normalized rows:
//   att = dot(n1_row, n2_row);  v = sigmoid(att/T);  out = v<=0.5 ? 0 : v
// fp32 everywhere (bf16/fp16 would flip 0.5-threshold edges; one flip
// costs rel_err ~9e-4 vs the 1e-3 budget).

#define NODE_CAP (1 << 17)   // 131072 >= N=100000
__device__ float4 g_nemb[NODE_CAP * 16];   // normalized rows (33.5 MB)
__device__ float  g_rinv[NODE_CAP];        // fallback path only

static __device__ __forceinline__ float decode_scalar(const void* p) {
    if (p == nullptr) return 1.0f;
    int iv = *(const int*)p;
    if (iv > 0 && iv < (1 << 23)) return (float)iv;   // int32-encoded
    return __int_as_float(iv);                        // f32 bit pattern
}

// ---- pass 1: normalize rows into scratch (8 lanes per node) ----
__global__ void __launch_bounds__(256) normalize_kernel(
    const float4* __restrict__ emb, float4* __restrict__ nemb, int N)
{
    int tid = blockIdx.x * blockDim.x + threadIdx.x;
    int nid = tid >> 3;
    int sub = tid & 7;
    if (nid >= N) return;

    const float4* a = emb + (size_t)nid * 16;
    float4 v0 = __ldg(&a[sub]);
    float4 v1 = __ldg(&a[sub + 8]);

    float n = v0.x*v0.x + v0.y*v0.y + v0.z*v0.z + v0.w*v0.w
            + v1.x*v1.x + v1.y*v1.y + v1.z*v1.z + v1.w*v1.w;
    #pragma unroll
    for (int m = 4; m > 0; m >>= 1)
        n += __shfl_xor_sync(0xFFFFFFFFu, n, m);

    float r = 1.0f / fmaxf(sqrtf(n), 1e-6f);

    float4* o = nemb + (size_t)nid * 16;
    o[sub]     = make_float4(v0.x*r, v0.y*r, v0.z*r, v0.w*r);
    o[sub + 8] = make_float4(v1.x*r, v1.y*r, v1.z*r, v1.w*r);
}

// ---- pass 2: flat edge kernel on normalized rows ----
// 8 lanes/edge; each LDG.128 covers one full 128B line of a row.
__global__ void __launch_bounds__(256) edge_kernel(
    const float4* __restrict__ nemb,  // normalized [N*16]
    const int*    __restrict__ ei,    // [2*E]
    const void*   __restrict__ temp,
    float*        __restrict__ out,   // [E]
    int E)
{
    int tid = blockIdx.x * blockDim.x + threadIdx.x;
    int eid = tid >> 3;
    int sub = tid & 7;
    if (eid >= E) return;

    int i1 = __ldg(&ei[eid]);
    int i2 = __ldg(&ei[E + eid]);

    const float4* a = nemb + (size_t)i1 * 16;
    const float4* b = nemb + (size_t)i2 * 16;

    float4 a0 = __ldg(&a[sub]);
    float4 a1 = __ldg(&a[sub + 8]);
    float4 b0 = __ldg(&b[sub]);
    float4 b1 = __ldg(&b[sub + 8]);

    float dot = a0.x*b0.x + a0.y*b0.y + a0.z*b0.z + a0.w*b0.w
              + a1.x*b1.x + a1.y*b1.y + a1.z*b1.z + a1.w*b1.w;

    #pragma unroll
    for (int m = 4; m > 0; m >>= 1)
        dot += __shfl_xor_sync(0xFFFFFFFFu, dot, m);

    if (sub == 0) {
        float invT = 1.0f / decode_scalar(temp);
        float v = 1.0f / (1.0f + __expf(-dot * invT));
        out[eid] = (v <= 0.5f) ? 0.0f : v;
    }
}

// ---- fallback for N beyond scratch cap (R5 scheme with rinv gathers) ----
__global__ void __launch_bounds__(256) norm_kernel_fb(
    const float4* __restrict__ emb, float* __restrict__ rinv, int N)
{
    int tid = blockIdx.x * blockDim.x + threadIdx.x;
    int nid = tid >> 3;
    int sub = tid & 7;
    if (nid >= N) return;
    const float4* a = emb + (size_t)nid * 16;
    float4 v0 = __ldg(&a[sub]);
    float4 v1 = __ldg(&a[sub + 8]);
    float n = v0.x*v0.x + v0.y*v0.y + v0.z*v0.z + v0.w*v0.w
            + v1.x*v1.x + v1.y*v1.y + v1.z*v1.z + v1.w*v1.w;
    #pragma unroll
    for (int m = 4; m > 0; m >>= 1)
        n += __shfl_xor_sync(0xFFFFFFFFu, n, m);
    if (sub == 0)
        rinv[nid] = 1.0f / fmaxf(sqrtf(n), 1e-6f);
}

__global__ void __launch_bounds__(256) edge_kernel_fb(
    const float4* __restrict__ emb, const int* __restrict__ ei,
    const float* __restrict__ rinv, const void* __restrict__ temp,
    float* __restrict__ out, int E)
{
    int tid = blockIdx.x * blockDim.x + threadIdx.x;
    int eid = tid >> 3;
    int sub = tid & 7;
    if (eid >= E) return;
    int i1 = __ldg(&ei[eid]);
    int i2 = __ldg(&ei[E + eid]);
    const float4* a = emb + (size_t)i1 * 16;
    const float4* b = emb + (size_t)i2 * 16;
    float4 a0 = __ldg(&a[sub]), a1 = __ldg(&a[sub + 8]);
    float4 b0 = __ldg(&b[sub]), b1 = __ldg(&b[sub + 8]);
    float dot = a0.x*b0.x + a0.y*b0.y + a0.z*b0.z + a0.w*b0.w
              + a1.x*b1.x + a1.y*b1.y + a1.z*b1.z + a1.w*b1.w;
    #pragma unroll
    for (int m = 4; m > 0; m >>= 1)
        dot += __shfl_xor_sync(0xFFFFFFFFu, dot, m);
    if (sub == 0) {
        float att = dot * __ldg(&rinv[i1]) * __ldg(&rinv[i2]);
        float v = 1.0f / (1.0f + __expf(-att / decode_scalar(temp)));
        out[eid] = (v <= 0.5f) ? 0.0f : v;
    }
}

extern "C" void kernel_launch(void* const* d_in, const int* in_sizes, int n_in,
                              void* d_out, int out_size)
{
    const float4* emb  = (const float4*)d_in[0];
    const int*    ei   = (const int*)d_in[1];
    const void*   temp = (n_in > 2) ? d_in[2] : nullptr;
    float*        out  = (float*)d_out;

    int N = in_sizes[0] / 64;
    int E = in_sizes[1] / 2;

    if (N <= NODE_CAP) {
        float4* nemb = nullptr;
        cudaGetSymbolAddress((void**)&nemb, g_nemb);

        {
            long long total = (long long)N * 8;
            int blocks = (int)((total + 255) / 256);
            normalize_kernel<<<blocks, 256>>>(emb, nemb, N);
        }
        {
            long long total = (long long)E * 8;
            int blocks = (int)((total + 255) / 256);
            edge_kernel<<<blocks, 256>>>(nemb, ei, temp, out, E);
        }
    } else {
        float* rinv = nullptr;
        cudaGetSymbolAddress((void**)&rinv, g_rinv);
        {
            long long total = (long long)N * 8;
            int blocks = (int)((total + 255) / 256);
            norm_kernel_fb<<<blocks, 256>>>(emb, rinv, N);
        }
        {
            long long total = (long long)E * 8;
            int blocks = (int)((total + 255) / 256);
            edge_kernel_fb<<<blocks, 256>>>(emb, ei, rinv, temp, out, E);
        }
    }
}